// round 1
// baseline (speedup 1.0000x reference)
#include <cuda_runtime.h>
#include <cuda_bf16.h>
#include <math.h>

// Problem constants
#define Fn 500
#define Hn 2000
#define FH 2500      // F + H
#define Dn 64
#define An 64
#define Bn 4096

// Scratch (device globals; no allocation allowed)
__device__ float g_pre_f[Fn * Dn];      // pre_f + bw  [500,64]
__device__ float g_pre_w[FH * Dn];      // pre_w       [2500,64]
__device__ float g_full [FH * Dn];      // concat(feat_emb, hid_emb)
__device__ float g_ctx  [Fn * Dn];      // context     [500,64]

// ---------------------------------------------------------------------------
// Kernel 1: pre_f = feat@W1 + bw ; pre_w = full@W2 ; copy full
// blocks 0..2499  -> pre_w row j (and g_full row j)
// blocks 2500..2999 -> pre_f row i
// 64 threads per block, thread a = output column.
// ---------------------------------------------------------------------------
__global__ void k1_preproj(const float* __restrict__ feat,
                           const float* __restrict__ hid,
                           const float* __restrict__ Ww,
                           const float* __restrict__ bw)
{
    __shared__ float sx[Dn];
    const int b = blockIdx.x;
    const int a = threadIdx.x;

    if (b < FH) {
        const float* src = (b < Fn) ? (feat + b * Dn) : (hid + (b - Fn) * Dn);
        float v = src[a];
        g_full[b * Dn + a] = v;
        sx[a] = v;
        __syncthreads();
        float acc = 0.f;
        #pragma unroll
        for (int k = 0; k < Dn; k++)
            acc += sx[k] * Ww[(Dn + k) * An + a];   // W2 rows 64..127
        g_pre_w[b * Dn + a] = acc;
    } else {
        const int i = b - FH;
        sx[a] = feat[i * Dn + a];
        __syncthreads();
        float acc = bw[a];
        #pragma unroll
        for (int k = 0; k < Dn; k++)
            acc += sx[k] * Ww[k * An + a];          // W1 rows 0..63
        g_pre_f[i * Dn + a] = acc;
    }
}

// ---------------------------------------------------------------------------
// Kernel 2: per-row masked attention -> context[i,:]
// One block per i (500 blocks), 256 threads.
// Phase A: deterministic compaction of active j (mask != 0), sorted by j.
// Phase B: for each active j: s = sum_k tanh(pf[k]+pw[j,k])*Wu[k]; e = exp(s)
// Phase C: ssum tree-reduce; context[k] = (1/ssum) * sum_m e_m * full[j_m, k]
// ---------------------------------------------------------------------------
__global__ void k2_attn(const float* __restrict__ mask,
                        const float* __restrict__ Wu)
{
    __shared__ float s_pf[Dn];
    __shared__ float s_wu[Dn];
    __shared__ int   s_jlist[FH];
    __shared__ float s_elist[FH];
    __shared__ int   s_cnt;
    __shared__ int   s_wcnt[8];
    __shared__ int   s_woff[8];
    __shared__ float s_red[256];
    __shared__ float s_part[4][Dn];
    __shared__ float s_inv;

    const int i    = blockIdx.x;
    const int tid  = threadIdx.x;
    const int wid  = tid >> 5;
    const int lane = tid & 31;

    if (tid < Dn) {
        s_pf[tid] = g_pre_f[i * Dn + tid];
        s_wu[tid] = Wu[tid];
    }
    if (tid == 0) s_cnt = 0;
    __syncthreads();

    // ---- Phase A: deterministic compaction (chunks of 256, ordered by j)
    const float* mrow = mask + (size_t)i * FH;
    for (int base = 0; base < FH; base += 256) {
        int j = base + tid;
        bool act = (j < FH) && (mrow[j] != 0.0f);
        unsigned bal = __ballot_sync(0xffffffffu, act);
        int pre = __popc(bal & ((1u << lane) - 1u));
        if (lane == 0) s_wcnt[wid] = __popc(bal);
        __syncthreads();
        if (tid == 0) {
            int o = s_cnt;
            #pragma unroll
            for (int w = 0; w < 8; w++) { s_woff[w] = o; o += s_wcnt[w]; }
            s_cnt = o;
        }
        __syncthreads();
        if (act) s_jlist[s_woff[wid] + pre] = j;
        __syncthreads();
    }
    const int cnt = s_cnt;

    // ---- Phase B: tanh-dot + exp for active pairs (dense over threads)
    float local = 0.f;
    for (int m = tid; m < cnt; m += 256) {
        int j = s_jlist[m];
        const float4* prow = reinterpret_cast<const float4*>(g_pre_w + j * Dn);
        float s = 0.f;
        #pragma unroll
        for (int q = 0; q < 16; q++) {
            float4 pw = __ldg(prow + q);
            int k = q * 4;
            s += tanhf(s_pf[k + 0] + pw.x) * s_wu[k + 0];
            s += tanhf(s_pf[k + 1] + pw.y) * s_wu[k + 1];
            s += tanhf(s_pf[k + 2] + pw.z) * s_wu[k + 2];
            s += tanhf(s_pf[k + 3] + pw.w) * s_wu[k + 3];
        }
        float e = __expf(s);
        s_elist[m] = e;
        local += e;
    }

    // ---- ssum: deterministic tree reduction
    s_red[tid] = local;
    __syncthreads();
    #pragma unroll
    for (int off = 128; off > 0; off >>= 1) {
        if (tid < off) s_red[tid] += s_red[tid + off];
        __syncthreads();
    }
    if (tid == 0) {
        float ssum = s_red[0];
        s_inv = (ssum > 0.f) ? (1.0f / ssum) : 1.0f;
    }
    __syncthreads();

    // ---- Phase C: context accumulation (4 groups of 64 threads)
    {
        const int g = tid >> 6;      // 0..3
        const int k = tid & 63;      // 0..63
        float acc = 0.f;
        for (int m = g; m < cnt; m += 4)
            acc += s_elist[m] * g_full[s_jlist[m] * Dn + k];
        s_part[g][k] = acc;
        __syncthreads();
        if (tid < Dn) {
            float c = (s_part[0][tid] + s_part[1][tid] +
                       s_part[2][tid] + s_part[3][tid]) * s_inv;
            g_ctx[i * Dn + tid] = c;
        }
    }
}

// ---------------------------------------------------------------------------
// Kernel 3: out = values @ context   [4096,500] @ [500,64] -> [4096,64]
// 64 blocks x 256 threads. Block covers 64 rows x 64 cols.
// Thread: tx = tid%32 -> 2 cols (k0=2*tx), ty = tid/32 -> 8 rows.
// F tiled by 50 (10 tiles). values + context tiles in smem.
// ---------------------------------------------------------------------------
#define TF 50
__global__ void k3_out(const float* __restrict__ values, float* __restrict__ out)
{
    __shared__ float s_val[64][TF];
    __shared__ float s_ctx[TF][64];

    const int tid  = threadIdx.x;
    const int tx   = tid & 31;
    const int ty   = tid >> 5;
    const int k0   = tx * 2;
    const int row0 = blockIdx.x * 64;

    float2 acc[8];
    #pragma unroll
    for (int m = 0; m < 8; m++) acc[m] = make_float2(0.f, 0.f);

    for (int f0 = 0; f0 < Fn; f0 += TF) {
        // load values tile [64][TF]
        for (int idx = tid; idx < 64 * TF; idx += 256) {
            int r = idx / TF, f = idx % TF;
            s_val[r][f] = values[(size_t)(row0 + r) * Fn + f0 + f];
        }
        // load context tile [TF][64]
        for (int idx = tid; idx < TF * 64; idx += 256) {
            int f = idx >> 6, c = idx & 63;
            s_ctx[f][c] = g_ctx[(f0 + f) * Dn + c];
        }
        __syncthreads();

        #pragma unroll
        for (int f = 0; f < TF; f++) {
            float2 cc = *reinterpret_cast<const float2*>(&s_ctx[f][k0]);
            #pragma unroll
            for (int m = 0; m < 8; m++) {
                float v = s_val[ty * 8 + m][f];
                acc[m].x += v * cc.x;
                acc[m].y += v * cc.y;
            }
        }
        __syncthreads();
    }

    #pragma unroll
    for (int m = 0; m < 8; m++) {
        int r = row0 + ty * 8 + m;
        *reinterpret_cast<float2*>(&out[(size_t)r * Dn + k0]) = acc[m];
    }
}

// ---------------------------------------------------------------------------
extern "C" void kernel_launch(void* const* d_in, const int* in_sizes, int n_in,
                              void* d_out, int out_size)
{
    const float* values   = (const float*)d_in[0];   // [4096,500]
    const float* feat_emb = (const float*)d_in[1];   // [500,64]
    const float* hid_emb  = (const float*)d_in[2];   // [2000,64]
    const float* Ww       = (const float*)d_in[3];   // [128,64]
    const float* bw       = (const float*)d_in[4];   // [64]
    const float* Wu       = (const float*)d_in[5];   // [64,1]
    const float* mask     = (const float*)d_in[6];   // [500,2500,1]
    float* out            = (float*)d_out;           // [4096,64]

    k1_preproj<<<FH + Fn, 64>>>(feat_emb, hid_emb, Ww, bw);
    k2_attn<<<Fn, 256>>>(mask, Wu);
    k3_out<<<Bn / 64, 256>>>(values, out);
}

// round 2
// speedup vs baseline: 1.0320x; 1.0320x over previous
#include <cuda_runtime.h>
#include <cuda_bf16.h>
#include <math.h>

// Problem constants
#define Fn 500
#define Hn 2000
#define FH 2500      // F + H
#define Dn 64
#define An 64
#define Bn 4096

// Scratch (device globals; no allocation allowed)
__device__ float g_pre_f[Fn * Dn];      // pre_f + bw  [500,64]
__device__ float g_pre_w[FH * Dn];      // pre_w       [2500,64]
__device__ float g_full [FH * Dn];      // concat(feat_emb, hid_emb)
__device__ float g_ctx  [Fn * Dn];      // context     [500,64]
__device__ float g_pwmax[FH];           // per-row max |pre_w|

// ---------------- packed f32x2 helpers (Blackwell) ----------------
__device__ __forceinline__ unsigned long long pk2(float a, float b) {
    unsigned long long r;
    asm("mov.b64 %0, {%1,%2};" : "=l"(r) : "f"(a), "f"(b));
    return r;
}
__device__ __forceinline__ void upk2(unsigned long long v, float& a, float& b) {
    asm("mov.b64 {%0,%1}, %2;" : "=f"(a), "=f"(b) : "l"(v));
}
__device__ __forceinline__ unsigned long long f2fma(unsigned long long a,
                                                    unsigned long long b,
                                                    unsigned long long c) {
    unsigned long long d;
    asm("fma.rn.f32x2 %0, %1, %2, %3;" : "=l"(d) : "l"(a), "l"(b), "l"(c));
    return d;
}
__device__ __forceinline__ unsigned long long f2add(unsigned long long a,
                                                    unsigned long long b) {
    unsigned long long d;
    asm("add.rn.f32x2 %0, %1, %2;" : "=l"(d) : "l"(a), "l"(b));
    return d;
}
__device__ __forceinline__ unsigned long long f2mul(unsigned long long a,
                                                    unsigned long long b) {
    unsigned long long d;
    asm("mul.rn.f32x2 %0, %1, %2;" : "=l"(d) : "l"(a), "l"(b));
    return d;
}

// ---------------------------------------------------------------------------
// Kernel 1: pre_w = full@W2 (rows j, + |.|max per row); pre_f = feat@W1 + bw
// 256 threads = 4 rows x 64 cols. Blocks 0..624 -> pre_w, 625..749 -> pre_f.
// ---------------------------------------------------------------------------
__global__ __launch_bounds__(256) void k1_preproj(const float* __restrict__ feat,
                                                  const float* __restrict__ hid,
                                                  const float* __restrict__ Ww,
                                                  const float* __restrict__ bw)
{
    __shared__ float sx[4][Dn];
    __shared__ float s_m[8];
    const int b    = blockIdx.x;
    const int tid  = threadIdx.x;
    const int g    = tid >> 6;    // row within block (0..3)
    const int a    = tid & 63;    // output column
    const int wid  = tid >> 5;
    const int lane = tid & 31;

    if (b < 625) {
        const int row = b * 4 + g;                 // 0..2499
        float v = (row < Fn) ? feat[row * Dn + a] : hid[(row - Fn) * Dn + a];
        g_full[row * Dn + a] = v;
        sx[g][a] = v;
        __syncthreads();
        float acc = 0.f;
        #pragma unroll
        for (int k = 0; k < Dn; k++)
            acc += sx[g][k] * Ww[(Dn + k) * An + a];   // W2 rows 64..127
        g_pre_w[row * Dn + a] = acc;
        // per-row max |pre_w| (64 threads = 2 warps per row)
        float m = fabsf(acc);
        #pragma unroll
        for (int off = 16; off > 0; off >>= 1)
            m = fmaxf(m, __shfl_xor_sync(0xffffffffu, m, off));
        if (lane == 0) s_m[wid] = m;
        __syncthreads();
        if (tid < 4) g_pwmax[b * 4 + tid] = fmaxf(s_m[2 * tid], s_m[2 * tid + 1]);
    } else {
        const int row = (b - 625) * 4 + g;         // 0..499
        sx[g][a] = feat[row * Dn + a];
        __syncthreads();
        float acc = bw[a];
        #pragma unroll
        for (int k = 0; k < Dn; k++)
            acc += sx[g][k] * Ww[k * An + a];          // W1 rows 0..63
        g_pre_f[row * Dn + a] = acc;
    }
}

// ---------------------------------------------------------------------------
// Kernel 2: masked attention -> context[i,:]. One block per i, 256 threads.
// Phase A: single-pass deterministic compaction of active j.
// Phase B: warp-per-item; lane owns k-pair; packed poly tanh; shfl reduce.
// Phase C: context accumulation (4 groups of 64 cols).
// ---------------------------------------------------------------------------
__global__ __launch_bounds__(256) void k2_attn(const float* __restrict__ mask,
                                               const float* __restrict__ Wu)
{
    __shared__ float s_pf[Dn];
    __shared__ float s_wu[Dn];
    __shared__ int   s_jlist[FH];
    __shared__ float s_elist[FH];
    __shared__ int   s_warpbase[9];
    __shared__ float s_wsum[8];
    __shared__ float s_pfmax;
    __shared__ float s_inv;
    __shared__ float s_part[4][Dn];

    const int i    = blockIdx.x;
    const int tid  = threadIdx.x;
    const int wid  = tid >> 5;
    const int lane = tid & 31;

    if (tid < Dn) {
        s_pf[tid] = g_pre_f[i * Dn + tid];
        s_wu[tid] = Wu[tid];
    }
    __syncthreads();

    // max |pre_f| (warp 0)
    if (wid == 0) {
        float m = fmaxf(fabsf(s_pf[lane]), fabsf(s_pf[lane + 32]));
        #pragma unroll
        for (int off = 16; off > 0; off >>= 1)
            m = fmaxf(m, __shfl_xor_sync(0xffffffffu, m, off));
        if (lane == 0) s_pfmax = m;
    }

    // ---- Phase A: single-pass compaction (deterministic order)
    const float* mrow = mask + (size_t)i * FH;
    unsigned flags = 0;
    #pragma unroll
    for (int c = 0; c < 10; c++) {
        int j = c * 256 + tid;
        if (j < FH && mrow[j] != 0.0f) flags |= (1u << c);
    }
    const int cl = __popc(flags);
    int inc = cl;
    #pragma unroll
    for (int off = 1; off < 32; off <<= 1) {
        int v = __shfl_up_sync(0xffffffffu, inc, off);
        if (lane >= off) inc += v;
    }
    if (lane == 31) s_warpbase[wid + 1] = inc;
    __syncthreads();
    if (tid == 0) {
        s_warpbase[0] = 0;
        #pragma unroll
        for (int w = 1; w <= 8; w++) s_warpbase[w] += s_warpbase[w - 1];
    }
    __syncthreads();
    {
        int off = s_warpbase[wid] + inc - cl;
        #pragma unroll
        for (int c = 0; c < 10; c++)
            if ((flags >> c) & 1u) s_jlist[off++] = c * 256 + tid;
    }
    __syncthreads();
    const int cnt = s_warpbase[8];

    // ---- Phase B: warp-per-item packed tanh-dot + exp
    const float pf0 = s_pf[2 * lane], pf1 = s_pf[2 * lane + 1];
    const float wu0 = s_wu[2 * lane], wu1 = s_wu[2 * lane + 1];
    const unsigned long long pfp = pk2(pf0, pf1);
    const unsigned long long wup = pk2(wu0, wu1);
    const unsigned long long C3  = pk2(-0.33333334f, -0.33333334f);
    const unsigned long long C5  = pk2( 0.13333334f,  0.13333334f);
    const unsigned long long C7  = pk2(-0.05396825f, -0.05396825f);
    const unsigned long long ONE = pk2(1.0f, 1.0f);
    const float pfmax = s_pfmax;
    float wsum = 0.f;

    for (int m = wid; m < cnt; m += 8) {
        const int j = s_jlist[m];
        const float2 pw = __ldg(((const float2*)(g_pre_w + j * Dn)) + lane);
        float s;
        if (pfmax + __ldg(&g_pwmax[j]) > 0.45f) {
            // rare accurate path
            s = tanhf(pf0 + pw.x) * wu0 + tanhf(pf1 + pw.y) * wu1;
        } else {
            unsigned long long xp = f2add(pfp, pk2(pw.x, pw.y));
            unsigned long long t  = f2mul(xp, xp);
            unsigned long long p  = f2fma(t, C7, C5);
            p = f2fma(t, p, C3);
            p = f2fma(t, p, ONE);
            unsigned long long y  = f2mul(xp, p);
            unsigned long long acc = f2mul(y, wup);
            float a0, a1; upk2(acc, a0, a1);
            s = a0 + a1;
        }
        #pragma unroll
        for (int off = 16; off > 0; off >>= 1)
            s += __shfl_xor_sync(0xffffffffu, s, off);
        if (lane == 0) {
            float e = expf(s);
            s_elist[m] = e;
            wsum += e;
        }
    }
    if (lane == 0) s_wsum[wid] = wsum;
    __syncthreads();
    if (tid == 0) {
        float ss = 0.f;
        #pragma unroll
        for (int w = 0; w < 8; w++) ss += s_wsum[w];
        s_inv = (ss > 0.f) ? (1.0f / ss) : 1.0f;
    }
    __syncthreads();

    // ---- Phase C: context accumulation
    {
        const int g = tid >> 6;      // 0..3
        const int k = tid & 63;
        float acc = 0.f;
        for (int m = g; m < cnt; m += 4)
            acc += s_elist[m] * __ldg(&g_full[s_jlist[m] * Dn + k]);
        s_part[g][k] = acc;
        __syncthreads();
        if (tid < Dn) {
            g_ctx[i * Dn + tid] = (s_part[0][tid] + s_part[1][tid] +
                                   s_part[2][tid] + s_part[3][tid]) * s_inv;
        }
    }
}

// ---------------------------------------------------------------------------
// Kernel 3: out = values @ context  [4096,500]@[500,64] -> [4096,64]
// 128 blocks x 32 rows x 64 cols; 256 threads; per-thread 2 rows x 4 cols
// using packed f32x2 FFMA.
// ---------------------------------------------------------------------------
#define TFk 50
__global__ __launch_bounds__(256) void k3_out(const float* __restrict__ values,
                                              float* __restrict__ out)
{
    __shared__ float s_val[32][TFk];
    __shared__ float s_ctx[TFk][Dn];

    const int tid  = threadIdx.x;
    const int tx   = tid & 15;          // 16 col groups
    const int ty   = tid >> 4;          // 16 row groups
    const int col0 = tx * 4;
    const int row0 = blockIdx.x * 32;
    const int r0   = ty * 2;

    unsigned long long acc00 = 0ull, acc01 = 0ull, acc10 = 0ull, acc11 = 0ull;

    for (int f0 = 0; f0 < Fn; f0 += TFk) {
        for (int idx = tid; idx < 32 * TFk; idx += 256) {
            int r = idx / TFk, f = idx % TFk;
            s_val[r][f] = values[(size_t)(row0 + r) * Fn + f0 + f];
        }
        for (int idx = tid; idx < TFk * Dn; idx += 256) {
            int f = idx >> 6, c = idx & 63;
            s_ctx[f][c] = g_ctx[(f0 + f) * Dn + c];
        }
        __syncthreads();

        #pragma unroll
        for (int f = 0; f < TFk; f++) {
            float v0 = s_val[r0][f];
            float v1 = s_val[r0 + 1][f];
            unsigned long long vp0 = pk2(v0, v0);
            unsigned long long vp1 = pk2(v1, v1);
            const unsigned long long* cp =
                reinterpret_cast<const unsigned long long*>(&s_ctx[f][col0]);
            unsigned long long c01 = cp[0];
            unsigned long long c23 = cp[1];
            acc00 = f2fma(vp0, c01, acc00);
            acc01 = f2fma(vp0, c23, acc01);
            acc10 = f2fma(vp1, c01, acc10);
            acc11 = f2fma(vp1, c23, acc11);
        }
        __syncthreads();
    }

    float a, b, c, d;
    upk2(acc00, a, b); upk2(acc01, c, d);
    *reinterpret_cast<float4*>(&out[(size_t)(row0 + r0) * Dn + col0]) =
        make_float4(a, b, c, d);
    upk2(acc10, a, b); upk2(acc11, c, d);
    *reinterpret_cast<float4*>(&out[(size_t)(row0 + r0 + 1) * Dn + col0]) =
        make_float4(a, b, c, d);
}

// ---------------------------------------------------------------------------
extern "C" void kernel_launch(void* const* d_in, const int* in_sizes, int n_in,
                              void* d_out, int out_size)
{
    const float* values   = (const float*)d_in[0];   // [4096,500]
    const float* feat_emb = (const float*)d_in[1];   // [500,64]
    const float* hid_emb  = (const float*)d_in[2];   // [2000,64]
    const float* Ww       = (const float*)d_in[3];   // [128,64]
    const float* bw       = (const float*)d_in[4];   // [64]
    const float* Wu       = (const float*)d_in[5];   // [64,1]
    const float* mask     = (const float*)d_in[6];   // [500,2500,1]
    float* out            = (float*)d_out;           // [4096,64]

    k1_preproj<<<750, 256>>>(feat_emb, hid_emb, Ww, bw);
    k2_attn<<<Fn, 256>>>(mask, Wu);
    k3_out<<<Bn / 32, 256>>>(values, out);
}